// round 10
// baseline (speedup 1.0000x reference)
#include <cuda_runtime.h>
#include <cstdint>

// ---------------------------------------------------------------------------
// C=12, L=32, D=32, NOUT=2. Counts are int32 on device (JAX x64-off).
// phase1 : dense per-read q[r][2] = W2_s . relu(W x_r + b) summed over L.
//          cp.async 3-stage pipeline, 2 reads (3KB) per stage, persistent
//          grid; scan side-blocks compute count offsets under the stream.
// phase2 : warp-per-allele ragged reduce (512-thread blocks).
// ---------------------------------------------------------------------------

#define MAXR 131072
#define MAXA 16384
#define GX   220               // persistent streaming blocks per source
__device__ float2 g_q0[MAXR];
__device__ float2 g_q1[MAXR];
__device__ int g_loc0[MAXA];             // exclusive offset within 256-chunk
__device__ int g_loc1[MAXA];
__device__ int g_btot0[MAXA / 256 + 1];  // per-chunk totals
__device__ int g_btot1[MAXA / 256 + 1];

__device__ __forceinline__ uint32_t f2tf32(float f) {
    uint32_t u;
    asm("cvt.rna.tf32.f32 %0, %1;" : "=r"(u) : "f"(f));
    return u;
}

__device__ __forceinline__ void mma_tf32(float c[4], const uint32_t a[4],
                                         uint32_t b0, uint32_t b1) {
    asm volatile(
        "mma.sync.aligned.m16n8k8.row.col.f32.tf32.tf32.f32 "
        "{%0,%1,%2,%3},{%4,%5,%6,%7},{%8,%9},{%0,%1,%2,%3};"
        : "+f"(c[0]), "+f"(c[1]), "+f"(c[2]), "+f"(c[3])
        : "r"(a[0]), "r"(a[1]), "r"(a[2]), "r"(a[3]), "r"(b0), "r"(b1));
}

__device__ __forceinline__ void cp16(uint32_t smem_addr, const void* g) {
    asm volatile("cp.async.ca.shared.global [%0], [%1], 16;"
                 :: "r"(smem_addr), "l"(g));
}

// ---------------------------------------------------------------------------
// Phase 1. blockIdx.x < NCH (y==0): scan one 256-allele count chunk, exit.
// Otherwise stream pairs of reads. Per warp per pair (3072B):
//   6x cp.async (16B ea, XOR-swizzled) -> wait/syncwarp -> 6x LDS.128 ->
//   24 cvt -> 32 tf32 MMAs -> relu+col-sum -> per-lane W2 dot ->
//   4-value deferred reduction (11 SHFL) -> predicated STG.32 (4 lanes).
// ---------------------------------------------------------------------------
__global__ __launch_bounds__(256, 3) void rc_phase1(
    const float* __restrict__ t0, const float* __restrict__ t1,
    const float* __restrict__ W0, const float* __restrict__ b0,
    const float* __restrict__ W1, const float* __restrict__ b1,
    const float* __restrict__ W2,
    const int* __restrict__ cnt0, const int* __restrict__ cnt1,
    int R, int A, int nch)
{
    const int tid = threadIdx.x;

    __shared__ float4 buf[8][3][192];    // 72KB: 8 warps x 3 stages x 2 reads
    __shared__ int s0[256], s1[256];     // scan path

    // ---- scan side-blocks (scheduled first, finish fast) ----
    if (blockIdx.x < (unsigned)nch) {
        if (blockIdx.y != 0) return;
        const int chunk = blockIdx.x;
        const int a = chunk * 256 + tid;
        const int v0 = (a < A) ? cnt0[a] : 0;
        const int v1 = (a < A) ? cnt1[a] : 0;
        s0[tid] = v0; s1[tid] = v1;
        __syncthreads();
        #pragma unroll
        for (int o = 1; o < 256; o <<= 1) {
            int p0 = (tid >= o) ? s0[tid - o] : 0;
            int p1 = (tid >= o) ? s1[tid - o] : 0;
            __syncthreads();
            s0[tid] += p0; s1[tid] += p1;
            __syncthreads();
        }
        if (a < A) { g_loc0[a] = s0[tid] - v0; g_loc1[a] = s1[tid] - v1; }
        if (tid == 255) { g_btot0[chunk] = s0[255]; g_btot1[chunk] = s1[255]; }
        return;
    }

    // ---- streaming ----
    const int s = blockIdx.y;
    const float* T  = s ? t1 : t0;
    const float* W  = s ? W1 : W0;
    const float* Bv = s ? b1 : b0;
    float* Outf     = s ? (float*)g_q1 : (float*)g_q0;

    const int wid = tid >> 5, lane = tid & 31;
    const int qp = lane >> 2, rp = lane & 3;
    const int g = lane >> 3, h = lane & 7;

    uint32_t af[2][2][4];
    #pragma unroll
    for (int m = 0; m < 2; m++) {
        int r0 = qp + 16 * m, r1 = r0 + 8;
        af[m][0][0] = f2tf32(W[r0 * 12 + rp]);
        af[m][0][1] = f2tf32(W[r1 * 12 + rp]);
        af[m][0][2] = f2tf32(W[r0 * 12 + rp + 4]);
        af[m][0][3] = f2tf32(W[r1 * 12 + rp + 4]);
        af[m][1][0] = f2tf32(W[r0 * 12 + rp + 8]);
        af[m][1][1] = f2tf32(W[r1 * 12 + rp + 8]);
        af[m][1][2] = (rp == 0) ? f2tf32(Bv[r0]) : 0u;
        af[m][1][3] = (rp == 0) ? f2tf32(Bv[r1]) : 0u;
    }
    const uint32_t bk1 = (rp == 0) ? f2tf32(1.0f) : 0u;

    float w2a[4], w2b[4];
    #pragma unroll
    for (int i = 0; i < 4; i++) {
        w2a[i] = W2[s * 32 + 8 * i + qp];
        w2b[i] = W2[64 + s * 32 + 8 * i + qp];
    }

    // swizzled slot indices within one 96-float4 read sub-buffer
    const int sw_st = h ^ (2 * g);
    const int sts0 = g * 8 + sw_st, sts1 = (g + 4) * 8 + sw_st,
              sts2 = (g + 8) * 8 + sw_st;
    const int sw_ld = qp ^ (2 * rp);
    const int lds0 = rp * 8 + sw_ld, lds1 = (rp + 4) * 8 + sw_ld,
              lds2 = (rp + 8) * 8 + sw_ld;

    // cp.async dst base addrs (stage 0); stage stride = 192*16 = 3072 B
    const uint32_t dA0 = (uint32_t)__cvta_generic_to_shared(&buf[wid][0][sts0]);
    const uint32_t dA1 = (uint32_t)__cvta_generic_to_shared(&buf[wid][0][sts1]);
    const uint32_t dA2 = (uint32_t)__cvta_generic_to_shared(&buf[wid][0][sts2]);

    const int WP = GX * 8;                     // warps per source
    const int P  = (R + 1) >> 1;               // pairs
    const int p0w = (blockIdx.x - nch) * 8 + wid;

    // prologue: stages 0,1
    #pragma unroll
    for (int st = 0; st < 2; st++) {
        int p = p0w + st * WP;
        if (p < P) {
            const float4* src = (const float4*)T + (size_t)p * 192;
            uint32_t so = st * 3072;
            cp16(dA0 + so, src + g * 8 + h);
            cp16(dA1 + so, src + (g + 4) * 8 + h);
            cp16(dA2 + so, src + (g + 8) * 8 + h);
            if (2 * p + 1 < R) {
                cp16(dA0 + so + 1536, src + 96 + g * 8 + h);
                cp16(dA1 + so + 1536, src + 96 + (g + 4) * 8 + h);
                cp16(dA2 + so + 1536, src + 96 + (g + 8) * 8 + h);
            }
        }
        asm volatile("cp.async.commit_group;" ::: "memory");
    }

    int p = p0w, stage = 0;
    while (p < P) {
        {
            int p2 = p + 2 * WP;
            int st = stage + 2; if (st >= 3) st -= 3;
            if (p2 < P) {
                const float4* src = (const float4*)T + (size_t)p2 * 192;
                uint32_t so = st * 3072;
                cp16(dA0 + so, src + g * 8 + h);
                cp16(dA1 + so, src + (g + 4) * 8 + h);
                cp16(dA2 + so, src + (g + 8) * 8 + h);
                if (2 * p2 + 1 < R) {
                    cp16(dA0 + so + 1536, src + 96 + g * 8 + h);
                    cp16(dA1 + so + 1536, src + 96 + (g + 4) * 8 + h);
                    cp16(dA2 + so + 1536, src + 96 + (g + 8) * 8 + h);
                }
            }
            asm volatile("cp.async.commit_group;" ::: "memory");
        }
        asm volatile("cp.async.wait_group 2;" ::: "memory");
        __syncwarp();

        const float4* B = &buf[wid][stage][0];
        float4 xA0 = B[lds0], xA1 = B[lds1], xA2 = B[lds2];
        float4 xB0 = B[96 + lds0], xB1 = B[96 + lds1], xB2 = B[96 + lds2];

        uint32_t uA0[4] = {f2tf32(xA0.x), f2tf32(xA0.y), f2tf32(xA0.z), f2tf32(xA0.w)};
        uint32_t uA1[4] = {f2tf32(xA1.x), f2tf32(xA1.y), f2tf32(xA1.z), f2tf32(xA1.w)};
        uint32_t uA2[4] = {f2tf32(xA2.x), f2tf32(xA2.y), f2tf32(xA2.z), f2tf32(xA2.w)};
        uint32_t uB0[4] = {f2tf32(xB0.x), f2tf32(xB0.y), f2tf32(xB0.z), f2tf32(xB0.w)};
        uint32_t uB1[4] = {f2tf32(xB1.x), f2tf32(xB1.y), f2tf32(xB1.z), f2tf32(xB1.w)};
        uint32_t uB2[4] = {f2tf32(xB2.x), f2tf32(xB2.y), f2tf32(xB2.z), f2tf32(xB2.w)};

        float accA[4] = {0.f, 0.f, 0.f, 0.f};
        float accB[4] = {0.f, 0.f, 0.f, 0.f};
        #pragma unroll
        for (int j = 0; j < 4; j++) {
            #pragma unroll
            for (int m = 0; m < 2; m++) {
                float c[4] = {0.f, 0.f, 0.f, 0.f};
                mma_tf32(c, af[m][0], uA0[j], uA1[j]);
                mma_tf32(c, af[m][1], uA2[j], bk1);
                accA[2 * m]     += fmaxf(c[0], 0.f) + fmaxf(c[1], 0.f);
                accA[2 * m + 1] += fmaxf(c[2], 0.f) + fmaxf(c[3], 0.f);
                float d[4] = {0.f, 0.f, 0.f, 0.f};
                mma_tf32(d, af[m][0], uB0[j], uB1[j]);
                mma_tf32(d, af[m][1], uB2[j], bk1);
                accB[2 * m]     += fmaxf(d[0], 0.f) + fmaxf(d[1], 0.f);
                accB[2 * m + 1] += fmaxf(d[2], 0.f) + fmaxf(d[3], 0.f);
            }
        }
        // per-lane W2 dot for both reads
        float vA0 = accA[0] * w2a[0] + accA[1] * w2a[1]
                  + accA[2] * w2a[2] + accA[3] * w2a[3];
        float vA1 = accA[0] * w2b[0] + accA[1] * w2b[1]
                  + accA[2] * w2b[2] + accA[3] * w2b[3];
        float vB0 = accB[0] * w2a[0] + accB[1] * w2a[1]
                  + accB[2] * w2a[2] + accB[3] * w2a[3];
        float vB1 = accB[0] * w2b[0] + accB[1] * w2b[1]
                  + accB[2] * w2b[2] + accB[3] * w2b[3];
        // 4-value deferred reduction: xor8/16 on all, select by lane-group,
        // xor1/2/4 within group; group j total lands in lanes j*8..j*8+7.
        vA0 += __shfl_xor_sync(0xffffffffu, vA0, 8);
        vA1 += __shfl_xor_sync(0xffffffffu, vA1, 8);
        vB0 += __shfl_xor_sync(0xffffffffu, vB0, 8);
        vB1 += __shfl_xor_sync(0xffffffffu, vB1, 8);
        vA0 += __shfl_xor_sync(0xffffffffu, vA0, 16);
        vA1 += __shfl_xor_sync(0xffffffffu, vA1, 16);
        vB0 += __shfl_xor_sync(0xffffffffu, vB0, 16);
        vB1 += __shfl_xor_sync(0xffffffffu, vB1, 16);
        float u = (g == 0) ? vA0 : (g == 1) ? vA1 : (g == 2) ? vB0 : vB1;
        u += __shfl_xor_sync(0xffffffffu, u, 1);
        u += __shfl_xor_sync(0xffffffffu, u, 2);
        u += __shfl_xor_sync(0xffffffffu, u, 4);
        // lanes 0,8,16,24 store floats 4p+0..3 (= Out[2p].xy, Out[2p+1].xy)
        const bool hasB = (2 * p + 1 < R);
        if (h == 0 && (g < 2 || hasB)) Outf[4 * p + g] = u;

        p += WP;
        stage++; if (stage >= 3) stage = 0;
    }
}

// ---------------------------------------------------------------------------
// Phase 2: warp-per-allele, 512-thread blocks (16 alleles/block, all within
// one 256-chunk). Offsets = chunk base (from totals) + local offset.
// ---------------------------------------------------------------------------
__global__ __launch_bounds__(512) void rc_phase2(
    const int* __restrict__ cnt0, const int* __restrict__ cnt1,
    const float* __restrict__ dm0, const float* __restrict__ dm1,
    const float* __restrict__ b2, float* __restrict__ out, int A)
{
    const int tid = threadIdx.x, wid = tid >> 5, lane = tid & 31;
    const int a = blockIdx.x * 16 + wid;
    if (a >= A) return;

    const int chunk = (blockIdx.x * 16) >> 8;
    int v0 = (lane < chunk) ? g_btot0[lane] : 0;
    int v1 = (lane < chunk) ? g_btot1[lane] : 0;
    #pragma unroll
    for (int o = 16; o; o >>= 1) {
        v0 += __shfl_xor_sync(0xffffffffu, v0, o);
        v1 += __shfl_xor_sync(0xffffffffu, v1, o);
    }

    const int off0 = v0 + g_loc0[a];
    const int off1 = v1 + g_loc1[a];
    const int c0 = cnt0[a], c1 = cnt1[a];

    float s00 = 0.f, s01 = 0.f, s10 = 0.f, s11 = 0.f;
    for (int i = lane; i < c0; i += 32) {
        float2 v = g_q0[off0 + i]; s00 += v.x; s01 += v.y;
    }
    for (int i = lane; i < c1; i += 32) {
        float2 v = g_q1[off1 + i]; s10 += v.x; s11 += v.y;
    }
    // 4-value deferred reduction
    s00 += __shfl_xor_sync(0xffffffffu, s00, 8);
    s01 += __shfl_xor_sync(0xffffffffu, s01, 8);
    s10 += __shfl_xor_sync(0xffffffffu, s10, 8);
    s11 += __shfl_xor_sync(0xffffffffu, s11, 8);
    s00 += __shfl_xor_sync(0xffffffffu, s00, 16);
    s01 += __shfl_xor_sync(0xffffffffu, s01, 16);
    s10 += __shfl_xor_sync(0xffffffffu, s10, 16);
    s11 += __shfl_xor_sync(0xffffffffu, s11, 16);
    const int g = lane >> 3;
    float u = (g == 0) ? s00 : (g == 1) ? s01 : (g == 2) ? s10 : s11;
    u += __shfl_xor_sync(0xffffffffu, u, 1);
    u += __shfl_xor_sync(0xffffffffu, u, 2);
    u += __shfl_xor_sync(0xffffffffu, u, 4);
    // lane0: u=s00 needs s10 (lane16); lane8: u=s01 needs s11 (lane24)
    float v2 = __shfl_sync(0xffffffffu, u, (lane & 15) + 16);
    if ((lane & 7) == 0 && lane < 16) {
        const float n0 = 1.0f / (dm0[a] * 32.f);
        const float n1 = 1.0f / (dm1[a] * 32.f);
        out[2 * a + (lane >> 3)] = b2[lane >> 3] + u * n0 + v2 * n1;
    }
}

// ---------------------------------------------------------------------------
extern "C" void kernel_launch(void* const* d_in, const int* in_sizes, int n_in,
                              void* d_out, int out_size) {
    const float* t0  = (const float*)d_in[0];
    const float* t1  = (const float*)d_in[1];
    const float* W0  = (const float*)d_in[2];
    const float* b0  = (const float*)d_in[3];
    const float* W1  = (const float*)d_in[4];
    const float* b1  = (const float*)d_in[5];
    const float* W2  = (const float*)d_in[6];
    const float* b2  = (const float*)d_in[7];
    const int*   c0  = (const int*)d_in[8];
    const int*   c1  = (const int*)d_in[9];
    const float* dm0 = (const float*)d_in[11];
    const float* dm1 = (const float*)d_in[12];
    float* out = (float*)d_out;

    const int A = in_sizes[8];
    const int R = in_sizes[0] / 384;   // reads per source (C*L = 384)
    const int nch = (A + 255) / 256;

    dim3 grid1(nch + GX, 2);
    rc_phase1<<<grid1, 256>>>(t0, t1, W0, b0, W1, b1, W2, c0, c1, R, A, nch);
    rc_phase2<<<(A + 15) / 16, 512>>>(c0, c1, dm0, dm1, b2, out, A);
}

// round 11
// speedup vs baseline: 1.0465x; 1.0465x over previous
#include <cuda_runtime.h>
#include <cstdint>

// ---------------------------------------------------------------------------
// C=12, L=32, D=32, NOUT=2. Counts are int32 on device (JAX x64-off).
// phase1 : dense per-read q[r][2] = W2_s . relu(W x_r + b) summed over L
//          (cp.async 3-stage per-warp pipeline, round-9 measured-best).
//          Scan side-blocks compute GLOBAL count offsets under the stream.
// phase2 : warp-per-allele ragged reduce using precomputed global offsets.
// ---------------------------------------------------------------------------

#define MAXR 131072
#define MAXA 16384
#define GX   1024              // streaming blocks in grid.x
__device__ float2 g_q0[MAXR];
__device__ float2 g_q1[MAXR];
__device__ int g_loc0[MAXA];   // GLOBAL exclusive offset per allele
__device__ int g_loc1[MAXA];

__device__ __forceinline__ uint32_t f2tf32(float f) {
    uint32_t u;
    asm("cvt.rna.tf32.f32 %0, %1;" : "=r"(u) : "f"(f));
    return u;
}

__device__ __forceinline__ void mma_tf32(float c[4], const uint32_t a[4],
                                         uint32_t b0, uint32_t b1) {
    asm volatile(
        "mma.sync.aligned.m16n8k8.row.col.f32.tf32.tf32.f32 "
        "{%0,%1,%2,%3},{%4,%5,%6,%7},{%8,%9},{%0,%1,%2,%3};"
        : "+f"(c[0]), "+f"(c[1]), "+f"(c[2]), "+f"(c[3])
        : "r"(a[0]), "r"(a[1]), "r"(a[2]), "r"(a[3]), "r"(b0), "r"(b1));
}

__device__ __forceinline__ void cp16(uint32_t smem_addr, const void* g) {
    asm volatile("cp.async.ca.shared.global [%0], [%1], 16;"
                 :: "r"(smem_addr), "l"(g));
}

// ---------------------------------------------------------------------------
// Phase 1. blockIdx.x >= GX (y==0): scan one 256-allele chunk, including its
// global base (reduce of all preceding counts), then exit. Otherwise stream.
// Streaming per warp per read (1536B): 3x cp.async (512B, XOR-swizzled) ->
// wait/syncwarp -> 3x LDS.128 -> 12 cvt -> 16 tf32 MMAs -> relu+col-sum ->
// per-lane W2 dot -> one 5-level butterfly -> lane0 STG.64.
// ---------------------------------------------------------------------------
__global__ __launch_bounds__(256) void rc_phase1(
    const float* __restrict__ t0, const float* __restrict__ t1,
    const float* __restrict__ W0, const float* __restrict__ b0,
    const float* __restrict__ W1, const float* __restrict__ b1,
    const float* __restrict__ W2,
    const int* __restrict__ cnt0, const int* __restrict__ cnt1,
    int R, int A)
{
    const int tid  = threadIdx.x;

    // ---- scan side-blocks (hidden under the streaming wave) ----
    if (blockIdx.x >= GX) {
        if (blockIdx.y != 0) return;
        const int chunk = blockIdx.x - GX;
        __shared__ int s0[256], s1[256];
        // global base: sum of all counts before this chunk
        int b0r = 0, b1r = 0;
        for (int j = tid; j < chunk * 256; j += 256) {
            b0r += cnt0[j]; b1r += cnt1[j];
        }
        s0[tid] = b0r; s1[tid] = b1r;
        __syncthreads();
        #pragma unroll
        for (int o = 128; o; o >>= 1) {
            if (tid < o) { s0[tid] += s0[tid + o]; s1[tid] += s1[tid + o]; }
            __syncthreads();
        }
        const int base0 = s0[0], base1 = s1[0];
        __syncthreads();
        // intra-chunk exclusive scan
        const int a = chunk * 256 + tid;
        const int v0 = (a < A) ? cnt0[a] : 0;
        const int v1 = (a < A) ? cnt1[a] : 0;
        s0[tid] = v0; s1[tid] = v1;
        __syncthreads();
        #pragma unroll
        for (int o = 1; o < 256; o <<= 1) {
            int p0 = (tid >= o) ? s0[tid - o] : 0;
            int p1 = (tid >= o) ? s1[tid - o] : 0;
            __syncthreads();
            s0[tid] += p0; s1[tid] += p1;
            __syncthreads();
        }
        if (a < A) {
            g_loc0[a] = base0 + s0[tid] - v0;
            g_loc1[a] = base1 + s1[tid] - v1;
        }
        return;
    }

    // ---- streaming (round-9 measured-best path, unchanged) ----
    const int s = blockIdx.y;
    const float* T  = s ? t1 : t0;
    const float* W  = s ? W1 : W0;
    const float* Bv = s ? b1 : b0;
    float2* Out     = s ? g_q1 : g_q0;

    const int wid  = tid >> 5, lane = tid & 31;
    const int qp   = lane >> 2, rp = lane & 3;
    const int g    = lane >> 3, h = lane & 7;

    __shared__ float4 buf[8][3][96];

    uint32_t af[2][2][4];
    #pragma unroll
    for (int m = 0; m < 2; m++) {
        int r0 = qp + 16 * m, r1 = r0 + 8;
        af[m][0][0] = f2tf32(W[r0 * 12 + rp]);
        af[m][0][1] = f2tf32(W[r1 * 12 + rp]);
        af[m][0][2] = f2tf32(W[r0 * 12 + rp + 4]);
        af[m][0][3] = f2tf32(W[r1 * 12 + rp + 4]);
        af[m][1][0] = f2tf32(W[r0 * 12 + rp + 8]);
        af[m][1][1] = f2tf32(W[r1 * 12 + rp + 8]);
        af[m][1][2] = (rp == 0) ? f2tf32(Bv[r0]) : 0u;
        af[m][1][3] = (rp == 0) ? f2tf32(Bv[r1]) : 0u;
    }
    const uint32_t bk1 = (rp == 0) ? f2tf32(1.0f) : 0u;

    float w2a[4], w2b[4];
    #pragma unroll
    for (int i = 0; i < 4; i++) {
        w2a[i] = W2[s * 32 + 8 * i + qp];
        w2b[i] = W2[64 + s * 32 + 8 * i + qp];
    }

    const int sw_st = h ^ (2 * g);
    const int sts0 = g * 8 + sw_st, sts1 = (g + 4) * 8 + sw_st,
              sts2 = (g + 8) * 8 + sw_st;
    const int sw_ld = qp ^ (2 * rp);
    const int lds0 = rp * 8 + sw_ld, lds1 = (rp + 4) * 8 + sw_ld,
              lds2 = (rp + 8) * 8 + sw_ld;

    uint32_t dst[3][3];
    #pragma unroll
    for (int st = 0; st < 3; st++) {
        dst[st][0] = (uint32_t)__cvta_generic_to_shared(&buf[wid][st][sts0]);
        dst[st][1] = (uint32_t)__cvta_generic_to_shared(&buf[wid][st][sts1]);
        dst[st][2] = (uint32_t)__cvta_generic_to_shared(&buf[wid][st][sts2]);
    }

    const int WT = GX * 8;
    const int r0w = blockIdx.x * 8 + wid;

    #pragma unroll
    for (int st = 0; st < 2; st++) {
        int rr = r0w + st * WT;
        if (rr < R) {
            const float4* p = (const float4*)T + (size_t)rr * 96;
            cp16(dst[st][0], p + g * 8 + h);
            cp16(dst[st][1], p + (g + 4) * 8 + h);
            cp16(dst[st][2], p + (g + 8) * 8 + h);
        }
        asm volatile("cp.async.commit_group;" ::: "memory");
    }

    int r = r0w, stage = 0;
    while (r < R) {
        {
            int rr = r + 2 * WT;
            int st = stage + 2; if (st >= 3) st -= 3;
            if (rr < R) {
                const float4* p = (const float4*)T + (size_t)rr * 96;
                cp16(dst[st][0], p + g * 8 + h);
                cp16(dst[st][1], p + (g + 4) * 8 + h);
                cp16(dst[st][2], p + (g + 8) * 8 + h);
            }
            asm volatile("cp.async.commit_group;" ::: "memory");
        }
        asm volatile("cp.async.wait_group 2;" ::: "memory");
        __syncwarp();

        const float4* B = buf[wid][stage];
        float4 x0 = B[lds0], x1 = B[lds1], x2 = B[lds2];
        uint32_t u0[4] = {f2tf32(x0.x), f2tf32(x0.y), f2tf32(x0.z), f2tf32(x0.w)};
        uint32_t u1[4] = {f2tf32(x1.x), f2tf32(x1.y), f2tf32(x1.z), f2tf32(x1.w)};
        uint32_t u2[4] = {f2tf32(x2.x), f2tf32(x2.y), f2tf32(x2.z), f2tf32(x2.w)};

        float acc[4] = {0.f, 0.f, 0.f, 0.f};
        #pragma unroll
        for (int j = 0; j < 4; j++) {
            #pragma unroll
            for (int m = 0; m < 2; m++) {
                float c[4] = {0.f, 0.f, 0.f, 0.f};
                mma_tf32(c, af[m][0], u0[j], u1[j]);
                mma_tf32(c, af[m][1], u2[j], bk1);
                acc[2 * m]     += fmaxf(c[0], 0.f) + fmaxf(c[1], 0.f);
                acc[2 * m + 1] += fmaxf(c[2], 0.f) + fmaxf(c[3], 0.f);
            }
        }
        float q0 = acc[0] * w2a[0] + acc[1] * w2a[1]
                 + acc[2] * w2a[2] + acc[3] * w2a[3];
        float q1 = acc[0] * w2b[0] + acc[1] * w2b[1]
                 + acc[2] * w2b[2] + acc[3] * w2b[3];
        #pragma unroll
        for (int o = 1; o <= 16; o <<= 1) {
            q0 += __shfl_xor_sync(0xffffffffu, q0, o);
            q1 += __shfl_xor_sync(0xffffffffu, q1, o);
        }
        if (lane == 0) Out[r] = make_float2(q0, q1);

        r += WT;
        stage++; if (stage >= 3) stage = 0;
    }
}

// ---------------------------------------------------------------------------
// Phase 2: warp-per-allele (8/block). Global offsets precomputed -> critical
// path is just loc/cnt load -> q gather -> 4-value deferred reduction.
// ---------------------------------------------------------------------------
__global__ __launch_bounds__(256) void rc_phase2(
    const int* __restrict__ cnt0, const int* __restrict__ cnt1,
    const float* __restrict__ dm0, const float* __restrict__ dm1,
    const float* __restrict__ b2, float* __restrict__ out, int A)
{
    const int tid = threadIdx.x, wid = tid >> 5, lane = tid & 31;
    const int a = blockIdx.x * 8 + wid;
    if (a >= A) return;

    const int off0 = g_loc0[a];
    const int off1 = g_loc1[a];
    const int c0 = cnt0[a], c1 = cnt1[a];

    float s00 = 0.f, s01 = 0.f, s10 = 0.f, s11 = 0.f;
    for (int i = lane; i < c0; i += 32) {
        float2 v = g_q0[off0 + i]; s00 += v.x; s01 += v.y;
    }
    for (int i = lane; i < c1; i += 32) {
        float2 v = g_q1[off1 + i]; s10 += v.x; s11 += v.y;
    }
    // 4-value deferred reduction: xor8/16 on all, select by lane-group,
    // xor1/2/4 within group; totals land in lanes 0,8,16,24.
    s00 += __shfl_xor_sync(0xffffffffu, s00, 8);
    s01 += __shfl_xor_sync(0xffffffffu, s01, 8);
    s10 += __shfl_xor_sync(0xffffffffu, s10, 8);
    s11 += __shfl_xor_sync(0xffffffffu, s11, 8);
    s00 += __shfl_xor_sync(0xffffffffu, s00, 16);
    s01 += __shfl_xor_sync(0xffffffffu, s01, 16);
    s10 += __shfl_xor_sync(0xffffffffu, s10, 16);
    s11 += __shfl_xor_sync(0xffffffffu, s11, 16);
    const int g = lane >> 3;
    float u = (g == 0) ? s00 : (g == 1) ? s01 : (g == 2) ? s10 : s11;
    u += __shfl_xor_sync(0xffffffffu, u, 1);
    u += __shfl_xor_sync(0xffffffffu, u, 2);
    u += __shfl_xor_sync(0xffffffffu, u, 4);
    // lane0 holds s00 (needs s10 from lane16); lane8 holds s01 (s11, lane24)
    float v2 = __shfl_sync(0xffffffffu, u, (lane & 15) + 16);
    if ((lane & 7) == 0 && lane < 16) {
        const float n0 = 1.0f / (dm0[a] * 32.f);
        const float n1 = 1.0f / (dm1[a] * 32.f);
        out[2 * a + (lane >> 3)] = b2[lane >> 3] + u * n0 + v2 * n1;
    }
}

// ---------------------------------------------------------------------------
extern "C" void kernel_launch(void* const* d_in, const int* in_sizes, int n_in,
                              void* d_out, int out_size) {
    const float* t0  = (const float*)d_in[0];
    const float* t1  = (const float*)d_in[1];
    const float* W0  = (const float*)d_in[2];
    const float* b0  = (const float*)d_in[3];
    const float* W1  = (const float*)d_in[4];
    const float* b1  = (const float*)d_in[5];
    const float* W2  = (const float*)d_in[6];
    const float* b2  = (const float*)d_in[7];
    const int*   c0  = (const int*)d_in[8];
    const int*   c1  = (const int*)d_in[9];
    const float* dm0 = (const float*)d_in[11];
    const float* dm1 = (const float*)d_in[12];
    float* out = (float*)d_out;

    const int A = in_sizes[8];
    const int R = in_sizes[0] / 384;   // reads per source (C*L = 384)
    const int nChunks = (A + 255) / 256;

    dim3 grid1(GX + nChunks, 2);
    rc_phase1<<<grid1, 256>>>(t0, t1, W0, b0, W1, b1, W2, c0, c1, R, A);
    rc_phase2<<<(A + 7) / 8, 256>>>(c0, c1, dm0, dm1, b2, out, A);
}

// round 12
// speedup vs baseline: 1.1108x; 1.0614x over previous
#include <cuda_runtime.h>
#include <cstdint>

// ---------------------------------------------------------------------------
// C=12, L=32, D=32, NOUT=2. Counts are int32 on device (JAX x64-off).
// Single fused kernel:
//   streaming blocks : per-read q[r][2] = W2_s . relu(W x_r + b) summed over L
//                      (cp.async 3-stage pipeline, measured-best config)
//   scan blocks      : global count offsets (hidden under the stream)
//   phase2 blocks    : dispatched last; spin on completion counter, then
//                      warp-per-allele ragged reduce + normalize + head bias.
// Counter protocol is replay-safe (last phase2 block resets state).
// ---------------------------------------------------------------------------

#define MAXR 131072
#define MAXA 16384
#define GX   1024              // streaming blocks per source
__device__ float2 g_q0[MAXR];
__device__ float2 g_q1[MAXR];
__device__ int g_loc0[MAXA];   // GLOBAL exclusive offset per allele
__device__ int g_loc1[MAXA];
__device__ int g_ctr1;         // producers done (streaming + scan)
__device__ int g_ctr2;         // phase2 blocks done

__device__ __forceinline__ uint32_t f2tf32(float f) {
    uint32_t u;
    asm("cvt.rna.tf32.f32 %0, %1;" : "=r"(u) : "f"(f));
    return u;
}

__device__ __forceinline__ void mma_tf32(float c[4], const uint32_t a[4],
                                         uint32_t b0, uint32_t b1) {
    asm volatile(
        "mma.sync.aligned.m16n8k8.row.col.f32.tf32.tf32.f32 "
        "{%0,%1,%2,%3},{%4,%5,%6,%7},{%8,%9},{%0,%1,%2,%3};"
        : "+f"(c[0]), "+f"(c[1]), "+f"(c[2]), "+f"(c[3])
        : "r"(a[0]), "r"(a[1]), "r"(a[2]), "r"(a[3]), "r"(b0), "r"(b1));
}

__device__ __forceinline__ void cp16(uint32_t smem_addr, const void* g) {
    asm volatile("cp.async.ca.shared.global [%0], [%1], 16;"
                 :: "r"(smem_addr), "l"(g));
}

// ---------------------------------------------------------------------------
// grid.x = GX + nch + P2B, grid.y = 2.
//   y any, x <  GX        : stream source y
//   y==0,  GX <= x < GX+nch : scan chunk (x-GX); y==1 same range exits
//   y==1,  x >= GX+nch    : phase2 block (x-GX-nch); y==0 same range exits
// Phase2 blocks have the highest linear block ids -> dispatched last.
// ---------------------------------------------------------------------------
__global__ __launch_bounds__(256) void rc_fused(
    const float* __restrict__ t0, const float* __restrict__ t1,
    const float* __restrict__ W0, const float* __restrict__ b0,
    const float* __restrict__ W1, const float* __restrict__ b1,
    const float* __restrict__ W2,
    const int* __restrict__ cnt0, const int* __restrict__ cnt1,
    const float* __restrict__ dm0, const float* __restrict__ dm1,
    const float* __restrict__ b2, float* __restrict__ out,
    int R, int A, int nch, int S, int P2B)
{
    const int tid = threadIdx.x;

    if (blockIdx.x >= GX) {
        const int xs = blockIdx.x - GX;
        // ------------------- scan blocks (y==0) -------------------
        if (xs < nch) {
            if (blockIdx.y != 0) return;
            const int chunk = xs;
            __shared__ int s0[256], s1[256];
            int b0r = 0, b1r = 0;
            for (int j = tid; j < chunk * 256; j += 256) {
                b0r += cnt0[j]; b1r += cnt1[j];
            }
            s0[tid] = b0r; s1[tid] = b1r;
            __syncthreads();
            #pragma unroll
            for (int o = 128; o; o >>= 1) {
                if (tid < o) { s0[tid] += s0[tid + o]; s1[tid] += s1[tid + o]; }
                __syncthreads();
            }
            const int base0 = s0[0], base1 = s1[0];
            __syncthreads();
            const int a = chunk * 256 + tid;
            const int v0 = (a < A) ? cnt0[a] : 0;
            const int v1 = (a < A) ? cnt1[a] : 0;
            s0[tid] = v0; s1[tid] = v1;
            __syncthreads();
            #pragma unroll
            for (int o = 1; o < 256; o <<= 1) {
                int p0 = (tid >= o) ? s0[tid - o] : 0;
                int p1 = (tid >= o) ? s1[tid - o] : 0;
                __syncthreads();
                s0[tid] += p0; s1[tid] += p1;
                __syncthreads();
            }
            if (a < A) {
                g_loc0[a] = base0 + s0[tid] - v0;
                g_loc1[a] = base1 + s1[tid] - v1;
            }
            __threadfence();
            __syncthreads();
            if (tid == 0) atomicAdd(&g_ctr1, 1);
            return;
        }
        // ------------------- phase2 blocks (y==1) -------------------
        if (blockIdx.y != 1) return;
        const int p2 = xs - nch;

        if (tid == 0) {                      // spin until all producers done
            while (*(volatile int*)&g_ctr1 < S) __nanosleep(200);
        }
        __syncthreads();
        __threadfence();                      // acquire

        const int wid = tid >> 5, lane = tid & 31;
        const int a = p2 * 8 + wid;
        if (a < A) {
            const int off0 = g_loc0[a];
            const int off1 = g_loc1[a];
            const int c0 = cnt0[a], c1 = cnt1[a];

            float s00 = 0.f, s01 = 0.f, s10 = 0.f, s11 = 0.f;
            for (int i = lane; i < c0; i += 32) {
                float2 v = g_q0[off0 + i]; s00 += v.x; s01 += v.y;
            }
            for (int i = lane; i < c1; i += 32) {
                float2 v = g_q1[off1 + i]; s10 += v.x; s11 += v.y;
            }
            // 4-value deferred reduction; totals land in lanes 0,8,16,24
            s00 += __shfl_xor_sync(0xffffffffu, s00, 8);
            s01 += __shfl_xor_sync(0xffffffffu, s01, 8);
            s10 += __shfl_xor_sync(0xffffffffu, s10, 8);
            s11 += __shfl_xor_sync(0xffffffffu, s11, 8);
            s00 += __shfl_xor_sync(0xffffffffu, s00, 16);
            s01 += __shfl_xor_sync(0xffffffffu, s01, 16);
            s10 += __shfl_xor_sync(0xffffffffu, s10, 16);
            s11 += __shfl_xor_sync(0xffffffffu, s11, 16);
            const int g = lane >> 3;
            float u = (g == 0) ? s00 : (g == 1) ? s01 : (g == 2) ? s10 : s11;
            u += __shfl_xor_sync(0xffffffffu, u, 1);
            u += __shfl_xor_sync(0xffffffffu, u, 2);
            u += __shfl_xor_sync(0xffffffffu, u, 4);
            float v2 = __shfl_sync(0xffffffffu, u, (lane & 15) + 16);
            if ((lane & 7) == 0 && lane < 16) {
                const float n0 = 1.0f / (dm0[a] * 32.f);
                const float n1 = 1.0f / (dm1[a] * 32.f);
                out[2 * a + (lane >> 3)] = b2[lane >> 3] + u * n0 + v2 * n1;
            }
        }
        __threadfence();
        __syncthreads();
        if (tid == 0) {
            int v = atomicAdd(&g_ctr2, 1);
            if (v == P2B - 1) {               // last phase2 block: reset state
                g_ctr1 = 0;
                g_ctr2 = 0;
                __threadfence();
            }
        }
        return;
    }

    // ------------------- streaming blocks (round-9 measured-best) ----------
    const int s = blockIdx.y;
    const float* T  = s ? t1 : t0;
    const float* W  = s ? W1 : W0;
    const float* Bv = s ? b1 : b0;
    float2* Out     = s ? g_q1 : g_q0;

    const int wid  = tid >> 5, lane = tid & 31;
    const int qp   = lane >> 2, rp = lane & 3;
    const int g    = lane >> 3, h = lane & 7;

    __shared__ float4 buf[8][3][96];

    uint32_t af[2][2][4];
    #pragma unroll
    for (int m = 0; m < 2; m++) {
        int r0 = qp + 16 * m, r1 = r0 + 8;
        af[m][0][0] = f2tf32(W[r0 * 12 + rp]);
        af[m][0][1] = f2tf32(W[r1 * 12 + rp]);
        af[m][0][2] = f2tf32(W[r0 * 12 + rp + 4]);
        af[m][0][3] = f2tf32(W[r1 * 12 + rp + 4]);
        af[m][1][0] = f2tf32(W[r0 * 12 + rp + 8]);
        af[m][1][1] = f2tf32(W[r1 * 12 + rp + 8]);
        af[m][1][2] = (rp == 0) ? f2tf32(Bv[r0]) : 0u;
        af[m][1][3] = (rp == 0) ? f2tf32(Bv[r1]) : 0u;
    }
    const uint32_t bk1 = (rp == 0) ? f2tf32(1.0f) : 0u;

    float w2a[4], w2b[4];
    #pragma unroll
    for (int i = 0; i < 4; i++) {
        w2a[i] = W2[s * 32 + 8 * i + qp];
        w2b[i] = W2[64 + s * 32 + 8 * i + qp];
    }

    const int sw_st = h ^ (2 * g);
    const int sts0 = g * 8 + sw_st, sts1 = (g + 4) * 8 + sw_st,
              sts2 = (g + 8) * 8 + sw_st;
    const int sw_ld = qp ^ (2 * rp);
    const int lds0 = rp * 8 + sw_ld, lds1 = (rp + 4) * 8 + sw_ld,
              lds2 = (rp + 8) * 8 + sw_ld;

    uint32_t dst[3][3];
    #pragma unroll
    for (int st = 0; st < 3; st++) {
        dst[st][0] = (uint32_t)__cvta_generic_to_shared(&buf[wid][st][sts0]);
        dst[st][1] = (uint32_t)__cvta_generic_to_shared(&buf[wid][st][sts1]);
        dst[st][2] = (uint32_t)__cvta_generic_to_shared(&buf[wid][st][sts2]);
    }

    const int WT = GX * 8;
    const int r0w = blockIdx.x * 8 + wid;

    #pragma unroll
    for (int st = 0; st < 2; st++) {
        int rr = r0w + st * WT;
        if (rr < R) {
            const float4* p = (const float4*)T + (size_t)rr * 96;
            cp16(dst[st][0], p + g * 8 + h);
            cp16(dst[st][1], p + (g + 4) * 8 + h);
            cp16(dst[st][2], p + (g + 8) * 8 + h);
        }
        asm volatile("cp.async.commit_group;" ::: "memory");
    }

    int r = r0w, stage = 0;
    while (r < R) {
        {
            int rr = r + 2 * WT;
            int st = stage + 2; if (st >= 3) st -= 3;
            if (rr < R) {
                const float4* p = (const float4*)T + (size_t)rr * 96;
                cp16(dst[st][0], p + g * 8 + h);
                cp16(dst[st][1], p + (g + 4) * 8 + h);
                cp16(dst[st][2], p + (g + 8) * 8 + h);
            }
            asm volatile("cp.async.commit_group;" ::: "memory");
        }
        asm volatile("cp.async.wait_group 2;" ::: "memory");
        __syncwarp();

        const float4* B = buf[wid][stage];
        float4 x0 = B[lds0], x1 = B[lds1], x2 = B[lds2];
        uint32_t u0[4] = {f2tf32(x0.x), f2tf32(x0.y), f2tf32(x0.z), f2tf32(x0.w)};
        uint32_t u1[4] = {f2tf32(x1.x), f2tf32(x1.y), f2tf32(x1.z), f2tf32(x1.w)};
        uint32_t u2[4] = {f2tf32(x2.x), f2tf32(x2.y), f2tf32(x2.z), f2tf32(x2.w)};

        float acc[4] = {0.f, 0.f, 0.f, 0.f};
        #pragma unroll
        for (int j = 0; j < 4; j++) {
            #pragma unroll
            for (int m = 0; m < 2; m++) {
                float c[4] = {0.f, 0.f, 0.f, 0.f};
                mma_tf32(c, af[m][0], u0[j], u1[j]);
                mma_tf32(c, af[m][1], u2[j], bk1);
                acc[2 * m]     += fmaxf(c[0], 0.f) + fmaxf(c[1], 0.f);
                acc[2 * m + 1] += fmaxf(c[2], 0.f) + fmaxf(c[3], 0.f);
            }
        }
        float q0 = acc[0] * w2a[0] + acc[1] * w2a[1]
                 + acc[2] * w2a[2] + acc[3] * w2a[3];
        float q1 = acc[0] * w2b[0] + acc[1] * w2b[1]
                 + acc[2] * w2b[2] + acc[3] * w2b[3];
        #pragma unroll
        for (int o = 1; o <= 16; o <<= 1) {
            q0 += __shfl_xor_sync(0xffffffffu, q0, o);
            q1 += __shfl_xor_sync(0xffffffffu, q1, o);
        }
        if (lane == 0) Out[r] = make_float2(q0, q1);

        r += WT;
        stage++; if (stage >= 3) stage = 0;
    }

    __threadfence();
    __syncthreads();
    if (tid == 0) atomicAdd(&g_ctr1, 1);
}

// ---------------------------------------------------------------------------
extern "C" void kernel_launch(void* const* d_in, const int* in_sizes, int n_in,
                              void* d_out, int out_size) {
    const float* t0  = (const float*)d_in[0];
    const float* t1  = (const float*)d_in[1];
    const float* W0  = (const float*)d_in[2];
    const float* b0  = (const float*)d_in[3];
    const float* W1  = (const float*)d_in[4];
    const float* b1  = (const float*)d_in[5];
    const float* W2  = (const float*)d_in[6];
    const float* b2  = (const float*)d_in[7];
    const int*   c0  = (const int*)d_in[8];
    const int*   c1  = (const int*)d_in[9];
    const float* dm0 = (const float*)d_in[11];
    const float* dm1 = (const float*)d_in[12];
    float* out = (float*)d_out;

    const int A = in_sizes[8];
    const int R = in_sizes[0] / 384;   // reads per source (C*L = 384)
    const int nch = (A + 255) / 256;
    const int P2B = (A + 7) / 8;       // phase2 blocks
    const int S   = 2 * GX + nch;      // producer blocks to wait for

    dim3 grid(GX + nch + P2B, 2);
    rc_fused<<<grid, 256>>>(t0, t1, W0, b0, W1, b1, W2, c0, c1,
                            dm0, dm1, b2, out, R, A, nch, S, P2B);
}

// round 13
// speedup vs baseline: 1.1987x; 1.0791x over previous
#include <cuda_runtime.h>
#include <cstdint>

// ---------------------------------------------------------------------------
// C=12, L=32, D=32, NOUT=2. Counts are int32 on device (JAX x64-off).
// Single fused kernel (replay-safe counter protocol):
//   streaming blocks : per-read q[r][2] = W2_s . relu(W x_r + b) sum over L
//                      cp.async 3-stage pipeline, loop unrolled x3 so stage
//                      indices are compile-time; rolling prefetch pointer.
//   scan blocks      : global count offsets (hidden under the stream)
//   phase2 blocks    : dispatched last; spin on producer counter, then
//                      warp-per-allele ragged reduce + normalize + bias.
// ---------------------------------------------------------------------------

#define MAXR 131072
#define MAXA 16384
#define GX   1024              // streaming blocks per source
__device__ float2 g_q0[MAXR];
__device__ float2 g_q1[MAXR];
__device__ int g_loc0[MAXA];   // GLOBAL exclusive offset per allele
__device__ int g_loc1[MAXA];
__device__ int g_ctr1;         // producers done (streaming + scan)
__device__ int g_ctr2;         // phase2 blocks done

__device__ __forceinline__ uint32_t f2tf32(float f) {
    uint32_t u;
    asm("cvt.rna.tf32.f32 %0, %1;" : "=r"(u) : "f"(f));
    return u;
}

__device__ __forceinline__ void mma_tf32(float c[4], const uint32_t a[4],
                                         uint32_t b0, uint32_t b1) {
    asm volatile(
        "mma.sync.aligned.m16n8k8.row.col.f32.tf32.tf32.f32 "
        "{%0,%1,%2,%3},{%4,%5,%6,%7},{%8,%9},{%0,%1,%2,%3};"
        : "+f"(c[0]), "+f"(c[1]), "+f"(c[2]), "+f"(c[3])
        : "r"(a[0]), "r"(a[1]), "r"(a[2]), "r"(a[3]), "r"(b0), "r"(b1));
}

__device__ __forceinline__ void cp16(uint32_t smem_addr, const void* g) {
    asm volatile("cp.async.ca.shared.global [%0], [%1], 16;"
                 :: "r"(smem_addr), "l"(g));
}

// ---------------------------------------------------------------------------
// grid.x = GX + nch + P2B, grid.y = 2.
//   y any, x <  GX          : stream source y
//   y==0,  GX <= x < GX+nch : scan chunk (x-GX)
//   y==1,  x >= GX+nch      : phase2 block (x-GX-nch)  [dispatched last]
// ---------------------------------------------------------------------------
__global__ __launch_bounds__(256) void rc_fused(
    const float* __restrict__ t0, const float* __restrict__ t1,
    const float* __restrict__ W0, const float* __restrict__ b0,
    const float* __restrict__ W1, const float* __restrict__ b1,
    const float* __restrict__ W2,
    const int* __restrict__ cnt0, const int* __restrict__ cnt1,
    const float* __restrict__ dm0, const float* __restrict__ dm1,
    const float* __restrict__ b2, float* __restrict__ out,
    int R, int A, int nch, int S, int P2B)
{
    const int tid = threadIdx.x;

    if (blockIdx.x >= GX) {
        const int xs = blockIdx.x - GX;
        // ------------------- scan blocks (y==0) -------------------
        if (xs < nch) {
            if (blockIdx.y != 0) return;
            const int chunk = xs;
            __shared__ int s0[256], s1[256];
            int b0r = 0, b1r = 0;
            for (int j = tid; j < chunk * 256; j += 256) {
                b0r += cnt0[j]; b1r += cnt1[j];
            }
            s0[tid] = b0r; s1[tid] = b1r;
            __syncthreads();
            #pragma unroll
            for (int o = 128; o; o >>= 1) {
                if (tid < o) { s0[tid] += s0[tid + o]; s1[tid] += s1[tid + o]; }
                __syncthreads();
            }
            const int base0 = s0[0], base1 = s1[0];
            __syncthreads();
            const int a = chunk * 256 + tid;
            const int v0 = (a < A) ? cnt0[a] : 0;
            const int v1 = (a < A) ? cnt1[a] : 0;
            s0[tid] = v0; s1[tid] = v1;
            __syncthreads();
            #pragma unroll
            for (int o = 1; o < 256; o <<= 1) {
                int p0 = (tid >= o) ? s0[tid - o] : 0;
                int p1 = (tid >= o) ? s1[tid - o] : 0;
                __syncthreads();
                s0[tid] += p0; s1[tid] += p1;
                __syncthreads();
            }
            if (a < A) {
                g_loc0[a] = base0 + s0[tid] - v0;
                g_loc1[a] = base1 + s1[tid] - v1;
            }
            __threadfence();
            __syncthreads();
            if (tid == 0) atomicAdd(&g_ctr1, 1);
            return;
        }
        // ------------------- phase2 blocks (y==1) -------------------
        if (blockIdx.y != 1) return;
        const int p2 = xs - nch;

        if (tid == 0) {
            while (*(volatile int*)&g_ctr1 < S) __nanosleep(200);
        }
        __syncthreads();
        __threadfence();   // acquire

        const int wid = tid >> 5, lane = tid & 31;
        const int a = p2 * 8 + wid;
        if (a < A) {
            const int off0 = g_loc0[a];
            const int off1 = g_loc1[a];
            const int c0 = cnt0[a], c1 = cnt1[a];

            float s00 = 0.f, s01 = 0.f, s10 = 0.f, s11 = 0.f;
            for (int i = lane; i < c0; i += 32) {
                float2 v = g_q0[off0 + i]; s00 += v.x; s01 += v.y;
            }
            for (int i = lane; i < c1; i += 32) {
                float2 v = g_q1[off1 + i]; s10 += v.x; s11 += v.y;
            }
            s00 += __shfl_xor_sync(0xffffffffu, s00, 8);
            s01 += __shfl_xor_sync(0xffffffffu, s01, 8);
            s10 += __shfl_xor_sync(0xffffffffu, s10, 8);
            s11 += __shfl_xor_sync(0xffffffffu, s11, 8);
            s00 += __shfl_xor_sync(0xffffffffu, s00, 16);
            s01 += __shfl_xor_sync(0xffffffffu, s01, 16);
            s10 += __shfl_xor_sync(0xffffffffu, s10, 16);
            s11 += __shfl_xor_sync(0xffffffffu, s11, 16);
            const int g = lane >> 3;
            float u = (g == 0) ? s00 : (g == 1) ? s01 : (g == 2) ? s10 : s11;
            u += __shfl_xor_sync(0xffffffffu, u, 1);
            u += __shfl_xor_sync(0xffffffffu, u, 2);
            u += __shfl_xor_sync(0xffffffffu, u, 4);
            float v2 = __shfl_sync(0xffffffffu, u, (lane & 15) + 16);
            if ((lane & 7) == 0 && lane < 16) {
                const float n0 = 1.0f / (dm0[a] * 32.f);
                const float n1 = 1.0f / (dm1[a] * 32.f);
                out[2 * a + (lane >> 3)] = b2[lane >> 3] + u * n0 + v2 * n1;
            }
        }
        __threadfence();
        __syncthreads();
        if (tid == 0) {
            int v = atomicAdd(&g_ctr2, 1);
            if (v == P2B - 1) {            // last phase2 block: reset state
                g_ctr1 = 0;
                g_ctr2 = 0;
                __threadfence();
            }
        }
        return;
    }

    // ------------------- streaming blocks -------------------
    const int s = blockIdx.y;
    const float* T  = s ? t1 : t0;
    const float* W  = s ? W1 : W0;
    const float* Bv = s ? b1 : b0;
    float* OutF     = s ? (float*)g_q1 : (float*)g_q0;

    const int wid  = tid >> 5, lane = tid & 31;
    const int qp   = lane >> 2, rp = lane & 3;
    const int g    = lane >> 3, h = lane & 7;

    __shared__ float4 buf[8][3][96];

    uint32_t af[2][2][4];
    #pragma unroll
    for (int m = 0; m < 2; m++) {
        int r0 = qp + 16 * m, r1 = r0 + 8;
        af[m][0][0] = f2tf32(W[r0 * 12 + rp]);
        af[m][0][1] = f2tf32(W[r1 * 12 + rp]);
        af[m][0][2] = f2tf32(W[r0 * 12 + rp + 4]);
        af[m][0][3] = f2tf32(W[r1 * 12 + rp + 4]);
        af[m][1][0] = f2tf32(W[r0 * 12 + rp + 8]);
        af[m][1][1] = f2tf32(W[r1 * 12 + rp + 8]);
        af[m][1][2] = (rp == 0) ? f2tf32(Bv[r0]) : 0u;
        af[m][1][3] = (rp == 0) ? f2tf32(Bv[r1]) : 0u;
    }
    const uint32_t bk1 = (rp == 0) ? f2tf32(1.0f) : 0u;

    float w2a[4], w2b[4];
    #pragma unroll
    for (int i = 0; i < 4; i++) {
        w2a[i] = W2[s * 32 + 8 * i + qp];
        w2b[i] = W2[64 + s * 32 + 8 * i + qp];
    }

    const int sw_st = h ^ (2 * g);
    const int sts0 = g * 8 + sw_st, sts1 = (g + 4) * 8 + sw_st,
              sts2 = (g + 8) * 8 + sw_st;
    const int sw_ld = qp ^ (2 * rp);
    const int lds0 = rp * 8 + sw_ld, lds1 = (rp + 4) * 8 + sw_ld,
              lds2 = (rp + 8) * 8 + sw_ld;

    uint32_t dstc[3];    // per-stage base cp.async dst for slot 0
    #pragma unroll
    for (int st = 0; st < 3; st++)
        dstc[st] = (uint32_t)__cvta_generic_to_shared(&buf[wid][st][sts0]);
    const int d1 = (sts1 - sts0) * 16;   // byte deltas (lane-constant)
    const int d2 = (sts2 - sts0) * 16;

    const int WT = GX * 8;
    const int r0w = blockIdx.x * 8 + wid;
    const int goff = g * 8 + h;
    const float4* T4 = (const float4*)T;

    // prologue: stages 0,1 for reads r0w, r0w+WT
    #pragma unroll
    for (int st = 0; st < 2; st++) {
        int rr = r0w + st * WT;
        if (rr < R) {
            const float4* p = T4 + (size_t)rr * 96 + goff;
            cp16(dstc[st], p);
            cp16(dstc[st] + d1, p + 32);
            cp16(dstc[st] + d2, p + 64);
        }
        asm volatile("cp.async.commit_group;" ::: "memory");
    }

    int r = r0w;
    const float4* psrc = T4 + (size_t)(r0w + 2 * WT) * 96 + goff;

    while (r < R) {
        #pragma unroll
        for (int s3 = 0; s3 < 3; s3++) {
            if (r < R) {
                const int pf = (s3 + 2) % 3;        // compile-time
                if (r + 2 * WT < R) {
                    cp16(dstc[pf], psrc);
                    cp16(dstc[pf] + d1, psrc + 32);
                    cp16(dstc[pf] + d2, psrc + 64);
                }
                asm volatile("cp.async.commit_group;" ::: "memory");
                asm volatile("cp.async.wait_group 2;" ::: "memory");
                __syncwarp();

                const float4* B = buf[wid][s3];      // compile-time stage
                float4 x0 = B[lds0], x1 = B[lds1], x2 = B[lds2];
                uint32_t u0[4] = {f2tf32(x0.x), f2tf32(x0.y),
                                  f2tf32(x0.z), f2tf32(x0.w)};
                uint32_t u1[4] = {f2tf32(x1.x), f2tf32(x1.y),
                                  f2tf32(x1.z), f2tf32(x1.w)};
                uint32_t u2[4] = {f2tf32(x2.x), f2tf32(x2.y),
                                  f2tf32(x2.z), f2tf32(x2.w)};

                float acc[4] = {0.f, 0.f, 0.f, 0.f};
                #pragma unroll
                for (int j = 0; j < 4; j++) {
                    #pragma unroll
                    for (int m = 0; m < 2; m++) {
                        float c[4] = {0.f, 0.f, 0.f, 0.f};
                        mma_tf32(c, af[m][0], u0[j], u1[j]);
                        mma_tf32(c, af[m][1], u2[j], bk1);
                        acc[2 * m]     += fmaxf(c[0], 0.f) + fmaxf(c[1], 0.f);
                        acc[2 * m + 1] += fmaxf(c[2], 0.f) + fmaxf(c[3], 0.f);
                    }
                }
                float q0 = acc[0] * w2a[0] + acc[1] * w2a[1]
                         + acc[2] * w2a[2] + acc[3] * w2a[3];
                float q1 = acc[0] * w2b[0] + acc[1] * w2b[1]
                         + acc[2] * w2b[2] + acc[3] * w2b[3];
                // 2-value reduction: fold halves, then one 4-level chain
                q0 += __shfl_xor_sync(0xffffffffu, q0, 16);
                q1 += __shfl_xor_sync(0xffffffffu, q1, 16);
                float u = (lane < 16) ? q0 : q1;
                u += __shfl_xor_sync(0xffffffffu, u, 1);
                u += __shfl_xor_sync(0xffffffffu, u, 2);
                u += __shfl_xor_sync(0xffffffffu, u, 4);
                u += __shfl_xor_sync(0xffffffffu, u, 8);
                // lanes 0 and 16 store adjacent floats (one 8B transaction)
                if ((lane & 15) == 0) OutF[2 * r + (lane >> 4)] = u;
            }
            r += WT;
            psrc += (size_t)WT * 96;
        }
    }

    __threadfence();
    __syncthreads();
    if (tid == 0) atomicAdd(&g_ctr1, 1);
}

// ---------------------------------------------------------------------------
extern "C" void kernel_launch(void* const* d_in, const int* in_sizes, int n_in,
                              void* d_out, int out_size) {
    const float* t0  = (const float*)d_in[0];
    const float* t1  = (const float*)d_in[1];
    const float* W0  = (const float*)d_in[2];
    const float* b0  = (const float*)d_in[3];
    const float* W1  = (const float*)d_in[4];
    const float* b1  = (const float*)d_in[5];
    const float* W2  = (const float*)d_in[6];
    const float* b2  = (const float*)d_in[7];
    const int*   c0  = (const int*)d_in[8];
    const int*   c1  = (const int*)d_in[9];
    const float* dm0 = (const float*)d_in[11];
    const float* dm1 = (const float*)d_in[12];
    float* out = (float*)d_out;

    const int A = in_sizes[8];
    const int R = in_sizes[0] / 384;   // reads per source (C*L = 384)
    const int nch = (A + 255) / 256;
    const int P2B = (A + 7) / 8;       // phase2 blocks
    const int S   = 2 * GX + nch;      // producer blocks to wait for

    dim3 grid(GX + nch + P2B, 2);
    rc_fused<<<grid, 256>>>(t0, t1, W0, b0, W1, b1, W2, c0, c1,
                            dm0, dm1, b2, out, R, A, nch, S, P2B);
}